// round 2
// baseline (speedup 1.0000x reference)
#include <cuda_runtime.h>
#include <stdint.h>

#define FULLMASK 0xFFFFFFFFu
#define NBATCH 16
#define NPT 2048
#define KNNK 20
#define EPSV 1e-5f

// scratch (device globals: no allocation allowed)
__device__ float g_Ys[NBATCH * NPT * 32];
__device__ float g_Ps[NBATCH * NPT * 32];
__device__ int   g_knn[NBATCH * NPT * KNNK];

// pack (value desc, index asc) into one monotone u64 key
__device__ __forceinline__ unsigned long long mkkey(float v, int j) {
    unsigned u = __float_as_uint(v);
    unsigned mm = (unsigned)(((int)u) >> 31) | 0x80000000u;
    return (((unsigned long long)(u ^ mm)) << 32) | (unsigned)(NPT - 1 - j);
}

// ---------------- KNN: warp per row, reg-resident distances, cached top-3 ----------------
__global__ __launch_bounds__(256) void knn_kernel(const float* __restrict__ xyz) {
    __shared__ float4 spts[NPT];
    int b = blockIdx.x >> 5;          // 32 blocks per batch
    int chunk = blockIdx.x & 31;      // 64 rows per block
    const float* xb = xyz + (size_t)b * 3 * NPT;
    for (int i = threadIdx.x; i < NPT; i += 256) {
        float x = xb[i], y = xb[NPT + i], z = xb[2 * NPT + i];
        spts[i] = make_float4(x, y, z, x * x + y * y + z * z);
    }
    __syncthreads();
    int warp = threadIdx.x >> 5, lane = threadIdx.x & 31;
    #pragma unroll 1
    for (int rr = 0; rr < 8; rr++) {
        int n = chunk * 64 + warp * 8 + rr;
        float4 c = spts[n];
        float vals[64];
        unsigned long long k1 = 0, k2 = 0, k3 = 0;
        #pragma unroll
        for (int t = 0; t < 64; t++) {
            int j = t * 32 + lane;
            float4 p = spts[j];
            float dot = c.x * p.x;
            dot = fmaf(c.y, p.y, dot);
            dot = fmaf(c.z, p.z, dot);
            // pd = 2*dot - xx_i - xx_j  (same formula as reference)
            float pd = fmaf(2.0f, dot, -c.w) - p.w;
            vals[t] = pd;
            unsigned long long key = mkkey(pd, j);
            if (key > k3) {
                if (key > k2) { k3 = k2; if (key > k1) { k2 = k1; k1 = key; } else k2 = key; }
                else k3 = key;
            }
        }
        unsigned long long lastOwn = ~0ull;
        int obase = (b * NPT + n) * KNNK;
        #pragma unroll 1
        for (int r = 0; r < KNNK; r++) {
            unsigned long long m = k1;
            #pragma unroll
            for (int s = 16; s; s >>= 1) {
                unsigned long long o = __shfl_xor_sync(FULLMASK, m, s);
                if (o > m) m = o;
            }
            if (k1 == m) {  // unique winner (index embedded in key)
                g_knn[obase + r] = NPT - 1 - (int)(m & 0xFFFFFFFFull);
                lastOwn = k1;
                k1 = k2; k2 = k3; k3 = 0;
                if (k1 == 0) {  // cache exhausted: rescan own 64 values (rare)
                    #pragma unroll
                    for (int t = 0; t < 64; t++) {
                        unsigned long long key = mkkey(vals[t], t * 32 + lane);
                        if (key < lastOwn && key > k3) {
                            if (key > k2) { k3 = k2; if (key > k1) { k2 = k1; k1 = key; } else k2 = key; }
                            else k3 = key;
                        }
                    }
                }
            }
        }
    }
}

// ------------- precompute: Ys = s1*(W1a xf), Ps = s1*((W1b-W1a) xf) + shift1 -------------
__global__ __launch_bounds__(256) void pre_kernel(
    const float* __restrict__ xf, const float* __restrict__ W1,
    const float* __restrict__ g1, const float* __restrict__ b1,
    const float* __restrict__ m1, const float* __restrict__ v1) {
    __shared__ float W1T[128 * 32];  // [c][o] transposed for conflict-free LDS
    for (int i = threadIdx.x; i < 4096; i += 256) {
        int o = i & 31, cc = i >> 5;
        W1T[cc * 32 + o] = W1[o * 128 + cc];
    }
    __syncthreads();
    int warp = threadIdx.x >> 5, lane = threadIdx.x & 31;
    float s = g1[lane] * rsqrtf(v1[lane] + EPSV);
    float shift = fmaf(-m1[lane], s, b1[lane]);
    #pragma unroll 1
    for (int pp = 0; pp < 8; pp++) {
        int point = blockIdx.x * 64 + warp * 8 + pp;
        int b = point >> 11, n = point & (NPT - 1);
        const float* col = xf + (size_t)b * 64 * NPT + n;
        float y = 0.f, p = 0.f;
        #pragma unroll
        for (int cc = 0; cc < 64; cc++) {
            float xv = col[(size_t)cc * NPT];       // broadcast load
            float wa = W1T[cc * 32 + lane];         // W1[:,0:64]  (nbr - x part)
            float wb = W1T[(cc + 64) * 32 + lane];  // W1[:,64:128] (x part)
            y = fmaf(wa, xv, y);
            p = fmaf(wb - wa, xv, p);
        }
        g_Ys[point * 32 + lane] = y * s;
        g_Ps[point * 32 + lane] = fmaf(p, s, shift);
    }
}

// ------------- edge MLP: warp per point, lane = channel, smem float4 broadcasts -------------
__global__ __launch_bounds__(128) void mlp_kernel(
    const float* __restrict__ W2, const float* __restrict__ g2,
    const float* __restrict__ b2, const float* __restrict__ m2,
    const float* __restrict__ v2, const float* __restrict__ W3,
    float* __restrict__ out) {
    __shared__ float W2T[1024];   // [c][o], BN2 scale folded
    __shared__ float W3T[2048];   // [c][o]
    __shared__ float sh2s[32];
    __shared__ __align__(16) float hbuf[4][32];
    __shared__ __align__(16) float fbuf[4][32];
    for (int i = threadIdx.x; i < 1024; i += 128) {
        int o = i & 31, cc = i >> 5;
        float s2 = g2[o] * rsqrtf(v2[o] + EPSV);
        W2T[cc * 32 + o] = W2[o * 32 + cc] * s2;
    }
    for (int i = threadIdx.x; i < 2048; i += 128) {
        int o = i & 63, cc = i >> 6;
        W3T[cc * 64 + o] = W3[o * 32 + cc];
    }
    if (threadIdx.x < 32) {
        int o = threadIdx.x;
        float s2 = g2[o] * rsqrtf(v2[o] + EPSV);
        sh2s[o] = fmaf(-m2[o], s2, b2[o]);
    }
    __syncthreads();
    int warp = threadIdx.x >> 5, lane = threadIdx.x & 31;
    float w2r[32], w3a[32], w3b[32];
    #pragma unroll
    for (int cc = 0; cc < 32; cc++) {
        w2r[cc] = W2T[cc * 32 + lane];       // row lane of scaled W2
        w3a[cc] = W3T[cc * 64 + lane];       // row lane of W3
        w3b[cc] = W3T[cc * 64 + 32 + lane];  // row lane+32 of W3
    }
    float sh2 = sh2s[lane];
    const float4* h4 = (const float4*)hbuf[warp];
    const float4* f4 = (const float4*)fbuf[warp];
    #pragma unroll 1
    for (int pp = 0; pp < 8; pp++) {
        int point = (blockIdx.x * 4 + warp) * 8 + pp;
        int b = point >> 11, n = point & (NPT - 1);
        const float* YsB = g_Ys + (size_t)b * NPT * 32;
        float ps = g_Ps[point * 32 + lane];
        int myidx = 0;
        if (lane < KNNK) myidx = g_knn[point * KNNK + lane];
        int j0 = __shfl_sync(FULLMASK, myidx, 0);
        float ysn = YsB[j0 * 32 + lane];   // software-pipelined gather
        float a0 = __int_as_float(0xff800000), a1 = a0;  // -inf
        #pragma unroll 1
        for (int k = 0; k < KNNK; k++) {
            float ys = ysn;
            if (k + 1 < KNNK) {
                int jn = __shfl_sync(FULLMASK, myidx, k + 1);
                ysn = YsB[jn * 32 + lane];
            }
            float h = ys + ps;
            h = fmaxf(h, 0.2f * h);          // leaky relu
            hbuf[warp][lane] = h;
            __syncwarp();
            float acc = sh2;
            #pragma unroll
            for (int q = 0; q < 8; q++) {     // f2 = lrelu(W2' h + sh2)
                float4 hv = h4[q];
                acc = fmaf(w2r[4 * q + 0], hv.x, acc);
                acc = fmaf(w2r[4 * q + 1], hv.y, acc);
                acc = fmaf(w2r[4 * q + 2], hv.z, acc);
                acc = fmaf(w2r[4 * q + 3], hv.w, acc);
            }
            acc = fmaxf(acc, 0.2f * acc);
            __syncwarp();
            fbuf[warp][lane] = acc;
            __syncwarp();
            float t0 = 0.f, t1 = 0.f;
            #pragma unroll
            for (int q = 0; q < 8; q++) {     // f3 = W3 f2 (2 rows per lane)
                float4 fv = f4[q];
                t0 = fmaf(w3a[4 * q + 0], fv.x, t0);
                t1 = fmaf(w3b[4 * q + 0], fv.x, t1);
                t0 = fmaf(w3a[4 * q + 1], fv.y, t0);
                t1 = fmaf(w3b[4 * q + 1], fv.y, t1);
                t0 = fmaf(w3a[4 * q + 2], fv.z, t0);
                t1 = fmaf(w3b[4 * q + 2], fv.z, t1);
                t0 = fmaf(w3a[4 * q + 3], fv.w, t0);
                t1 = fmaf(w3b[4 * q + 3], fv.w, t1);
            }
            a0 = fmaxf(a0, t0);
            a1 = fmaxf(a1, t1);
        }
        // out[b][c][2n+u] = fmax[b][u*32+c][n]; lane holds c=lane (u=0: a0, u=1: a1)
        float2* op = (float2*)(out + (size_t)(b * 32 + lane) * (2 * NPT) + 2 * n);
        *op = make_float2(a0, a1);
    }
}

extern "C" void kernel_launch(void* const* d_in, const int* in_sizes, int n_in,
                              void* d_out, int out_size) {
    const float* xyz = (const float*)d_in[0];
    const float* xf  = (const float*)d_in[1];
    const float* W1  = (const float*)d_in[2];
    const float* g1  = (const float*)d_in[3];
    const float* b1  = (const float*)d_in[4];
    const float* m1  = (const float*)d_in[5];
    const float* v1  = (const float*)d_in[6];
    const float* W2  = (const float*)d_in[7];
    const float* g2  = (const float*)d_in[8];
    const float* b2  = (const float*)d_in[9];
    const float* m2  = (const float*)d_in[10];
    const float* v2  = (const float*)d_in[11];
    const float* W3  = (const float*)d_in[12];
    float* out = (float*)d_out;

    knn_kernel<<<512, 256>>>(xyz);
    pre_kernel<<<512, 256>>>(xf, W1, g1, b1, m1, v1);
    mlp_kernel<<<1024, 128>>>(W2, g2, b2, m2, v2, W3, out);
}

// round 3
// speedup vs baseline: 1.8181x; 1.8181x over previous
#include <cuda_runtime.h>
#include <stdint.h>

#define FULLMASK 0xFFFFFFFFu
#define NBATCH 16
#define NPT 2048
#define KNNK 20
#define EPSV 1e-5f

// scratch (device globals: no allocation allowed)
__device__ float g_Ys[NBATCH * NPT * 32];
__device__ float g_Ps[NBATCH * NPT * 32];
__device__ int   g_knn[NBATCH * NPT * KNNK];

// pack (value desc, index asc) into one monotone u64 key
__device__ __forceinline__ unsigned long long mkkey(float v, int j) {
    unsigned u = __float_as_uint(v);
    unsigned mm = (unsigned)(((int)u) >> 31) | 0x80000000u;
    return (((unsigned long long)(u ^ mm)) << 32) | (unsigned)(NPT - 1 - j);
}

// ---- packed f32x2 helpers (FFMA2) ----
__device__ __forceinline__ unsigned long long pack2(float a, float b) {
    unsigned long long r;
    asm("mov.b64 %0, {%1, %2};" : "=l"(r) : "f"(a), "f"(b));
    return r;
}
__device__ __forceinline__ void unpack2(unsigned long long v, float& a, float& b) {
    asm("mov.b64 {%0, %1}, %2;" : "=f"(a), "=f"(b) : "l"(v));
}
__device__ __forceinline__ unsigned long long fma2(unsigned long long a,
                                                   unsigned long long b,
                                                   unsigned long long c) {
    unsigned long long d;
    asm("fma.rn.f32x2 %0, %1, %2, %3;" : "=l"(d) : "l"(a), "l"(b), "l"(c));
    return d;
}

// ---------------- KNN: warp per row, smem points, top-3 cache + REDUX selection ----------------
__global__ __launch_bounds__(256) void knn_kernel(const float* __restrict__ xyz) {
    __shared__ float4 spts[NPT];
    int b = blockIdx.x >> 6;          // 64 blocks per batch
    int chunk = blockIdx.x & 63;      // 32 rows per block
    const float* xb = xyz + (size_t)b * 3 * NPT;
    for (int i = threadIdx.x; i < NPT; i += 256) {
        float x = xb[i], y = xb[NPT + i], z = xb[2 * NPT + i];
        spts[i] = make_float4(x, y, z, x * x + y * y + z * z);
    }
    __syncthreads();
    int warp = threadIdx.x >> 5, lane = threadIdx.x & 31;
    #pragma unroll 1
    for (int rr = 0; rr < 4; rr++) {
        int n = chunk * 32 + warp * 4 + rr;
        float4 c = spts[n];
        unsigned long long k1 = 0, k2 = 0, k3 = 0;
        #pragma unroll 4
        for (int t = 0; t < 64; t++) {
            int j = t * 32 + lane;
            float4 p = spts[j];
            float dot = c.x * p.x;
            dot = fmaf(c.y, p.y, dot);
            dot = fmaf(c.z, p.z, dot);
            float pd = fmaf(2.0f, dot, -c.w) - p.w;   // 2*dot - xx_i - xx_j
            unsigned long long key = mkkey(pd, j);
            if (key > k3) {
                if (key > k2) { k3 = k2; if (key > k1) { k2 = k1; k1 = key; } else k2 = key; }
                else k3 = key;
            }
        }
        unsigned long long lastOwn = ~0ull;
        int myout = 0;
        #pragma unroll 1
        for (int r = 0; r < KNNK; r++) {
            unsigned hi = (unsigned)(k1 >> 32);
            unsigned m = __reduce_max_sync(FULLMASK, hi);
            unsigned lo = (hi == m) ? (unsigned)k1 : 0u;
            unsigned l2 = __reduce_max_sync(FULLMASK, lo);  // max(2047-j) = min j among ties
            if (lane == r) myout = NPT - 1 - (int)l2;       // winner idx is warp-uniform
            if (hi == m && (unsigned)k1 == l2) {            // unique winner lane pops
                lastOwn = k1;
                k1 = k2; k2 = k3; k3 = 0;
                if (k1 == 0) {  // cache exhausted: rescan own 64 candidates (rare)
                    #pragma unroll 4
                    for (int t = 0; t < 64; t++) {
                        int j = t * 32 + lane;
                        float4 p = spts[j];
                        float dot = c.x * p.x;
                        dot = fmaf(c.y, p.y, dot);
                        dot = fmaf(c.z, p.z, dot);
                        float pd = fmaf(2.0f, dot, -c.w) - p.w;
                        unsigned long long key = mkkey(pd, j);
                        if (key < lastOwn && key > k3) {
                            if (key > k2) { k3 = k2; if (key > k1) { k2 = k1; k1 = key; } else k2 = key; }
                            else k3 = key;
                        }
                    }
                }
            }
        }
        if (lane < KNNK) g_knn[(b * NPT + n) * KNNK + lane] = myout;  // coalesced store
    }
}

// ------------- precompute: Ys = s1*(W1a xf), Ps = s1*((W1b-W1a) xf) + shift1 -------------
__global__ __launch_bounds__(256) void pre_kernel(
    const float* __restrict__ xf, const float* __restrict__ W1,
    const float* __restrict__ g1, const float* __restrict__ b1,
    const float* __restrict__ m1, const float* __restrict__ v1) {
    __shared__ float W1T[128 * 32];  // [c][o] transposed for conflict-free LDS
    for (int i = threadIdx.x; i < 4096; i += 256) {
        int o = i & 31, cc = i >> 5;
        W1T[cc * 32 + o] = W1[o * 128 + cc];
    }
    __syncthreads();
    int warp = threadIdx.x >> 5, lane = threadIdx.x & 31;
    float s = g1[lane] * rsqrtf(v1[lane] + EPSV);
    float shift = fmaf(-m1[lane], s, b1[lane]);
    #pragma unroll 1
    for (int pp = 0; pp < 8; pp++) {
        int point = blockIdx.x * 64 + warp * 8 + pp;
        int b = point >> 11, n = point & (NPT - 1);
        const float* col = xf + (size_t)b * 64 * NPT + n;
        float y = 0.f, p = 0.f;
        #pragma unroll
        for (int cc = 0; cc < 64; cc++) {
            float xv = col[(size_t)cc * NPT];       // broadcast load
            float wa = W1T[cc * 32 + lane];         // W1[:,0:64]  (nbr - x part)
            float wb = W1T[(cc + 64) * 32 + lane];  // W1[:,64:128] (x part)
            y = fmaf(wa, xv, y);
            p = fmaf(wb - wa, xv, p);
        }
        g_Ys[point * 32 + lane] = y * s;
        g_Ps[point * 32 + lane] = fmaf(p, s, shift);
    }
}

// ------------- edge MLP: warp per point, lane = channel, FFMA2 packed GEMVs -------------
__global__ __launch_bounds__(128) void mlp_kernel(
    const float* __restrict__ W2, const float* __restrict__ g2,
    const float* __restrict__ b2, const float* __restrict__ m2,
    const float* __restrict__ v2, const float* __restrict__ W3,
    float* __restrict__ out) {
    __shared__ float W2T[1024];   // [c][o], BN2 scale folded
    __shared__ float W3T[2048];   // [c][o]
    __shared__ float sh2s[32];
    __shared__ __align__(16) float hbuf[4][32];
    __shared__ __align__(16) float fbuf[4][32];
    for (int i = threadIdx.x; i < 1024; i += 128) {
        int o = i & 31, cc = i >> 5;
        float s2 = g2[o] * rsqrtf(v2[o] + EPSV);
        W2T[cc * 32 + o] = W2[o * 32 + cc] * s2;
    }
    for (int i = threadIdx.x; i < 2048; i += 128) {
        int o = i & 63, cc = i >> 6;
        W3T[cc * 64 + o] = W3[o * 32 + cc];
    }
    if (threadIdx.x < 32) {
        int o = threadIdx.x;
        float s2 = g2[o] * rsqrtf(v2[o] + EPSV);
        sh2s[o] = fmaf(-m2[o], s2, b2[o]);
    }
    __syncthreads();
    int warp = threadIdx.x >> 5, lane = threadIdx.x & 31;
    // pre-packed weight pairs (consecutive input channels -> f32x2 lanes)
    unsigned long long w2p[16], w3ap[16], w3bp[16];
    #pragma unroll
    for (int q = 0; q < 16; q++) {
        w2p[q]  = pack2(W2T[(2 * q) * 32 + lane],      W2T[(2 * q + 1) * 32 + lane]);
        w3ap[q] = pack2(W3T[(2 * q) * 64 + lane],      W3T[(2 * q + 1) * 64 + lane]);
        w3bp[q] = pack2(W3T[(2 * q) * 64 + 32 + lane], W3T[(2 * q + 1) * 64 + 32 + lane]);
    }
    float sh2 = sh2s[lane];
    const unsigned long long* h8 = (const unsigned long long*)hbuf[warp];
    const unsigned long long* f8 = (const unsigned long long*)fbuf[warp];
    #pragma unroll 1
    for (int pp = 0; pp < 8; pp++) {
        int point = (blockIdx.x * 4 + warp) * 8 + pp;
        int b = point >> 11, n = point & (NPT - 1);
        const float* YsB = g_Ys + (size_t)b * NPT * 32;
        float ps = g_Ps[point * 32 + lane];
        int myidx = 0;
        if (lane < KNNK) myidx = g_knn[point * KNNK + lane];
        int j0 = __shfl_sync(FULLMASK, myidx, 0);
        float ysn = YsB[j0 * 32 + lane];   // software-pipelined gather
        float a0 = __int_as_float(0xff800000), a1 = a0;  // -inf
        #pragma unroll 1
        for (int k = 0; k < KNNK; k++) {
            float ys = ysn;
            if (k + 1 < KNNK) {
                int jn = __shfl_sync(FULLMASK, myidx, k + 1);
                ysn = YsB[jn * 32 + lane];
            }
            float h = ys + ps;
            h = fmaxf(h, 0.2f * h);          // leaky relu
            hbuf[warp][lane] = h;
            __syncwarp();
            unsigned long long acc2 = 0;
            #pragma unroll
            for (int q = 0; q < 16; q++)     // f2 = lrelu(W2' h + sh2), packed
                acc2 = fma2(w2p[q], h8[q], acc2);
            float ax, ay;
            unpack2(acc2, ax, ay);
            float acc = ax + ay + sh2;
            acc = fmaxf(acc, 0.2f * acc);
            fbuf[warp][lane] = acc;
            __syncwarp();
            unsigned long long t0p = 0, t1p = 0;
            #pragma unroll
            for (int q = 0; q < 16; q++) {   // f3 = W3 f2 (2 rows per lane), packed
                unsigned long long fv = f8[q];
                t0p = fma2(w3ap[q], fv, t0p);
                t1p = fma2(w3bp[q], fv, t1p);
            }
            float t0x, t0y, t1x, t1y;
            unpack2(t0p, t0x, t0y);
            unpack2(t1p, t1x, t1y);
            a0 = fmaxf(a0, t0x + t0y);
            a1 = fmaxf(a1, t1x + t1y);
        }
        // out[b][c][2n+u] = fmax[b][u*32+c][n]; lane holds c=lane (u=0: a0, u=1: a1)
        float2* op = (float2*)(out + (size_t)(b * 32 + lane) * (2 * NPT) + 2 * n);
        *op = make_float2(a0, a1);
    }
}

extern "C" void kernel_launch(void* const* d_in, const int* in_sizes, int n_in,
                              void* d_out, int out_size) {
    const float* xyz = (const float*)d_in[0];
    const float* xf  = (const float*)d_in[1];
    const float* W1  = (const float*)d_in[2];
    const float* g1  = (const float*)d_in[3];
    const float* b1  = (const float*)d_in[4];
    const float* m1  = (const float*)d_in[5];
    const float* v1  = (const float*)d_in[6];
    const float* W2  = (const float*)d_in[7];
    const float* g2  = (const float*)d_in[8];
    const float* b2  = (const float*)d_in[9];
    const float* m2  = (const float*)d_in[10];
    const float* v2  = (const float*)d_in[11];
    const float* W3  = (const float*)d_in[12];
    float* out = (float*)d_out;

    knn_kernel<<<1024, 256>>>(xyz);
    pre_kernel<<<512, 256>>>(xf, W1, g1, b1, m1, v1);
    mlp_kernel<<<1024, 128>>>(W2, g2, b2, m2, v2, W3, out);
}